// round 2
// baseline (speedup 1.0000x reference)
#include <cuda_runtime.h>
#include <cuda_bf16.h>

// CapsuleRoutingPooling collapses analytically:
// softmax over a size-1 axis == 1 -> routing loop is a no-op.
// out = squash( 2x2 sum-pool over spatial of the D=16 vectors ).
//
// Shapes: B=16, C=64, H=W=64, D=16, k=2 -> nH=nW=32,
// output vectors = 16*64*32*32 = 1,048,576.
// 4 threads per output vector (one float4 each); each thread processes
// TWO vectors (near half + far half) for ILP/MLP=8. Streaming cache
// hints (__ldcs/__stcs): zero reuse, keep L2 clean.

static constexpr int NVEC = 16 * 64 * 32 * 32;     // 1,048,576 output vectors
static constexpr int HALF = NVEC / 2;              // vectors per half
static constexpr int NTHREADS_TOTAL = HALF * 4;    // 2,097,152 threads

__device__ __forceinline__ void pool_one(const float4* __restrict__ in4,
                                         int v, int lane,
                                         float4& s) {
    int bc = v >> 10;          // b*C + c
    int t  = v & 1023;
    int nh = t >> 5;
    int nw = t & 31;
    // row (b,c,h) = 256 float4s; w step = 4 float4s
    int base4 = (bc * 64 + (nh << 1)) * 256 + (nw << 3) + lane;

    float4 p00 = __ldcs(&in4[base4]);
    float4 p01 = __ldcs(&in4[base4 + 4]);
    float4 p10 = __ldcs(&in4[base4 + 256]);
    float4 p11 = __ldcs(&in4[base4 + 260]);

    s.x = (p00.x + p01.x) + (p10.x + p11.x);
    s.y = (p00.y + p01.y) + (p10.y + p11.y);
    s.z = (p00.z + p01.z) + (p10.z + p11.z);
    s.w = (p00.w + p01.w) + (p10.w + p11.w);
}

__device__ __forceinline__ float4 squash4(float4 s) {
    float sq = s.x * s.x + s.y * s.y + s.z * s.z + s.w * s.w;
    sq += __shfl_xor_sync(0xffffffffu, sq, 1);
    sq += __shfl_xor_sync(0xffffffffu, sq, 2);
    float scale = sq / ((1.0f + sq) * (sqrtf(sq) + 1e-8f));
    float4 o;
    o.x = s.x * scale; o.y = s.y * scale;
    o.z = s.z * scale; o.w = s.w * scale;
    return o;
}

__global__ void __launch_bounds__(256)
capsule_pool_squash_kernel(const float* __restrict__ inp, float* __restrict__ out) {
    int gid  = blockIdx.x * blockDim.x + threadIdx.x;
    int v0   = gid >> 2;          // first output vector (near half)
    int lane = gid & 3;
    int v1   = v0 + HALF;         // second output vector (far half)

    const float4* __restrict__ in4 = (const float4*)inp;

    // Compute both index sets, then issue all 8 loads back-to-back (MLP=8).
    int bc0 = v0 >> 10, t0 = v0 & 1023;
    int bc1 = v1 >> 10, t1 = v1 & 1023;
    int base0 = (bc0 * 64 + ((t0 >> 5) << 1)) * 256 + ((t0 & 31) << 3) + lane;
    int base1 = (bc1 * 64 + ((t1 >> 5) << 1)) * 256 + ((t1 & 31) << 3) + lane;

    float4 a00 = __ldcs(&in4[base0]);
    float4 a01 = __ldcs(&in4[base0 + 4]);
    float4 a10 = __ldcs(&in4[base0 + 256]);
    float4 a11 = __ldcs(&in4[base0 + 260]);
    float4 b00 = __ldcs(&in4[base1]);
    float4 b01 = __ldcs(&in4[base1 + 4]);
    float4 b10 = __ldcs(&in4[base1 + 256]);
    float4 b11 = __ldcs(&in4[base1 + 260]);

    float4 sa, sb;
    sa.x = (a00.x + a01.x) + (a10.x + a11.x);
    sa.y = (a00.y + a01.y) + (a10.y + a11.y);
    sa.z = (a00.z + a01.z) + (a10.z + a11.z);
    sa.w = (a00.w + a01.w) + (a10.w + a11.w);
    sb.x = (b00.x + b01.x) + (b10.x + b11.x);
    sb.y = (b00.y + b01.y) + (b10.y + b11.y);
    sb.z = (b00.z + b01.z) + (b10.z + b11.z);
    sb.w = (b00.w + b01.w) + (b10.w + b11.w);

    float4 oa = squash4(sa);
    float4 ob = squash4(sb);

    float4* __restrict__ out4 = (float4*)out;
    __stcs(&out4[(v0 << 2) + lane], oa);
    __stcs(&out4[(v1 << 2) + lane], ob);
}

extern "C" void kernel_launch(void* const* d_in, const int* in_sizes, int n_in,
                              void* d_out, int out_size) {
    const float* inp = (const float*)d_in[0];
    float* out = (float*)d_out;
    int threads = 256;
    int blocks = NTHREADS_TOTAL / threads;   // 8192
    capsule_pool_squash_kernel<<<blocks, threads>>>(inp, out);
}